// round 13
// baseline (speedup 1.0000x reference)
#include <cuda_runtime.h>
#include <cstdint>
#include <math.h>

#define ENT   20000
#define ENTP  20064       // padded to NCT*BN
#define RELN  500
#define DIM   64
#define TSZ   256
#define BM    128
#define BN    96          // 12 n8-tiles; 209 col tiles cover 20064 >= 20000
#define NCT   209
#define PW    36          // smem pitch in 4B words (72 bf16); 36%32=4 -> bank-bijective

// SMEM word offsets
#define OFF_A   0                     // [128][PW] bf16x2 words of hr
#define OFF_B   (BM * PW)             // [96][PW] bf16x2 words of ent tile
#define OFF_NH  (OFF_B + BN * PW)     // [128] f32
#define OFF_NE  (OFF_NH + BM)         // [96] f32
#define SM_WORDS (OFF_NE + BN)
#define SM_BYTES (SM_WORDS * 4)       // 33152

// Precomputed globals (no allocation allowed)
__device__ uint32_t g_entb[ENTP * 32];   // ent_emb as bf16x2 words, zero-padded
__device__ uint32_t g_hrb[TSZ * 32];     // hr = ent[h]+rel[r] as bf16x2 words
__device__ float    g_ne[ENTP];          // ||ent_j||^2 (0 on pad)
__device__ float    g_nh[TSZ];           // ||hr_i||^2

__device__ __forceinline__ float sqrt_approx(float x) {
    float y;
    asm("sqrt.approx.f32 %0, %1;" : "=f"(y) : "f"(x));
    return y;
}
__device__ __forceinline__ uint32_t bf16x2(float lo, float hi) {
    uint32_t u;
    asm("cvt.rn.bf16x2.f32 %0, %1, %2;" : "=r"(u) : "f"(hi), "f"(lo));
    return u;
}
__device__ __forceinline__ void mma_bf16(float* d, const uint32_t* a,
                                         uint32_t b0, uint32_t b1) {
    asm volatile(
        "mma.sync.aligned.m16n8k16.row.col.f32.bf16.bf16.f32 "
        "{%0,%1,%2,%3}, {%4,%5,%6,%7}, {%8,%9}, {%0,%1,%2,%3};"
        : "+f"(d[0]), "+f"(d[1]), "+f"(d[2]), "+f"(d[3])
        : "r"(a[0]), "r"(a[1]), "r"(a[2]), "r"(a[3]), "r"(b0), "r"(b1));
}

// ---------------------------------------------------------------------------
// prep: blocks [0,79)  -> convert ent row j to bf16x2 + ne[j] (zeros on pad)
//       blocks [79,95) -> hr rows (16 thr/row): bf16x2 + nh
// ---------------------------------------------------------------------------
__global__ void __launch_bounds__(256)
prep_kernel(const float* __restrict__ ent, const float* __restrict__ rel,
            const int* __restrict__ h, const int* __restrict__ r) {
    const int b   = blockIdx.x;
    const int tid = threadIdx.x;

    if (b < 79) {
        int j = b * 256 + tid;          // 0..20223
        if (j < ENTP) {
            uint32_t w[32];
            float s = 0.0f;
            if (j < ENT) {
                const float4* e = (const float4*)(ent + (size_t)j * DIM);
#pragma unroll
                for (int k = 0; k < 16; k++) {
                    float4 v = e[k];
                    s += v.x * v.x + v.y * v.y + v.z * v.z + v.w * v.w;
                    w[2 * k]     = bf16x2(v.x, v.y);
                    w[2 * k + 1] = bf16x2(v.z, v.w);
                }
            } else {
#pragma unroll
                for (int k = 0; k < 32; k++) w[k] = 0u;
            }
            uint4* dst = (uint4*)(g_entb + (size_t)j * 32);
#pragma unroll
            for (int k = 0; k < 8; k++)
                dst[k] = make_uint4(w[4 * k], w[4 * k + 1], w[4 * k + 2], w[4 * k + 3]);
            g_ne[j] = s;
        }
    } else {
        int row = (b - 79) * 16 + (tid >> 4);   // 0..255
        int q   = tid & 15;
        int hI  = h[row];
        int rI  = r[row];
        float4 a = *(const float4*)(ent + (size_t)hI * DIM + q * 4);
        float4 c = *(const float4*)(rel + (size_t)rI * DIM + q * 4);
        float4 v = make_float4(a.x + c.x, a.y + c.y, a.z + c.z, a.w + c.w);
        float s = v.x * v.x + v.y * v.y + v.z * v.z + v.w * v.w;
#pragma unroll
        for (int o = 8; o >= 1; o >>= 1) s += __shfl_xor_sync(0xffffffffu, s, o, 16);
        if (q == 0) g_nh[row] = s;
        uint32_t* dst = g_hrb + (size_t)row * 32 + q * 2;
        dst[0] = bf16x2(v.x, v.y);
        dst[1] = bf16x2(v.z, v.w);
    }
}

// ---------------------------------------------------------------------------
// score[i][j] = sqrt(nh[i] + ne[j] - 2 * dot(hr_i, ent_j))
// All operands pre-packed bf16; load phase is pure coalesced LDG.128+STS.128.
// Tile 128 x 96 per CTA; 418 CTAs, 3 resident per SM.
// ---------------------------------------------------------------------------
__global__ void __launch_bounds__(256, 3)
transe_mma_kernel(float* __restrict__ out) {
    extern __shared__ uint32_t smw[];
    uint32_t* sA  = smw + OFF_A;
    uint32_t* sB  = smw + OFF_B;
    float*    sNH = (float*)(smw + OFF_NH);
    float*    sNE = (float*)(smw + OFF_NE);

    const int tid  = threadIdx.x;
    const int lane = tid & 31;
    const int warp = tid >> 5;
    const int jT   = blockIdx.x * BN;
    const int iT   = blockIdx.y * BM;

    // ---- B tile: 96 rows x 32 words = 768 uint4 ----
#pragma unroll
    for (int it = 0; it < 3; it++) {
        int idx = it * 256 + tid;
        int row = idx >> 3;
        int q   = idx & 7;
        uint4 v = *(const uint4*)(g_entb + (size_t)(jT + row) * 32 + q * 4);
        *(uint4*)(sB + row * PW + q * 4) = v;
    }
    // ---- A tile: 128 rows x 32 words = 1024 uint4 ----
#pragma unroll
    for (int it = 0; it < 4; it++) {
        int idx = it * 256 + tid;
        int row = idx >> 3;
        int q   = idx & 7;
        uint4 v = *(const uint4*)(g_hrb + (size_t)(iT + row) * 32 + q * 4);
        *(uint4*)(sA + row * PW + q * 4) = v;
    }
    if (tid < BN)  sNE[tid] = g_ne[jT + tid];
    if (tid < BM)  sNH[tid] = g_nh[iT + tid];
    __syncthreads();

    // ---- mainloop: warp (wm, wn); warp tile 32 x 48; 4 k16 chunks ----
    const int wm  = warp >> 1;      // 0..3
    const int wn  = warp & 1;       // 0..1
    const int grp = lane >> 2;      // 0..7
    const int t4  = lane & 3;       // 0..3

    float d[2][6][4];
#pragma unroll
    for (int f = 0; f < 2; f++)
#pragma unroll
        for (int g = 0; g < 6; g++)
#pragma unroll
            for (int e = 0; e < 4; e++) d[f][g][e] = 0.0f;

#pragma unroll
    for (int ch = 0; ch < 4; ch++) {
        const int k0 = ch * 8 + t4;     // bf16x2-word index within row
        uint32_t a[2][4];
#pragma unroll
        for (int f = 0; f < 2; f++) {
            int base = (wm * 32 + f * 16 + grp) * PW;
            a[f][0] = sA[base + k0];
            a[f][1] = sA[base + 8 * PW + k0];
            a[f][2] = sA[base + k0 + 4];
            a[f][3] = sA[base + 8 * PW + k0 + 4];
        }
#pragma unroll
        for (int g = 0; g < 6; g++) {
            int bbase = (wn * 48 + g * 8 + grp) * PW;
            uint32_t b0 = sB[bbase + k0];
            uint32_t b1 = sB[bbase + k0 + 4];
            mma_bf16(d[0][g], a[0], b0, b1);
            mma_bf16(d[1][g], a[1], b0, b1);
        }
    }

    // ---- epilogue: c0/c1 at (row, 2*t4 / +1); c2/c3 at row+8 ----
#pragma unroll
    for (int f = 0; f < 2; f++) {
        int rl0 = wm * 32 + f * 16 + grp;
        int rl1 = rl0 + 8;
        float nh0 = sNH[rl0];
        float nh1 = sNH[rl1];
        float* o0 = out + (size_t)(iT + rl0) * ENT + jT;
        float* o1 = out + (size_t)(iT + rl1) * ENT + jT;
#pragma unroll
        for (int g = 0; g < 6; g++) {
            int cl = wn * 48 + g * 8 + t4 * 2;
            if (jT + cl < ENT) {
                float2 ne2 = *(const float2*)(sNE + cl);
                float2 s0, s1;
                s0.x = sqrt_approx(fmaxf(nh0 + ne2.x - 2.0f * d[f][g][0], 0.0f));
                s0.y = sqrt_approx(fmaxf(nh0 + ne2.y - 2.0f * d[f][g][1], 0.0f));
                s1.x = sqrt_approx(fmaxf(nh1 + ne2.x - 2.0f * d[f][g][2], 0.0f));
                s1.y = sqrt_approx(fmaxf(nh1 + ne2.y - 2.0f * d[f][g][3], 0.0f));
                *(float2*)(o0 + cl) = s0;
                *(float2*)(o1 + cl) = s1;
            }
        }
    }
}

// ---------------------------------------------------------------------------
// Inputs (metadata order): ent_emb f32[20000*64], rel_emb f32[500*64],
//                          h i32[256], r i32[256], t i32[256], (batch_size)
// Output: f32[256*20000]
// ---------------------------------------------------------------------------
extern "C" void kernel_launch(void* const* d_in, const int* in_sizes, int n_in,
                              void* d_out, int out_size) {
    const float* ent = (const float*)d_in[0];
    const float* rel = (const float*)d_in[1];
    const int*   h   = (const int*)d_in[2];
    const int*   r   = (const int*)d_in[3];
    float*       out = (float*)d_out;

    cudaFuncSetAttribute(transe_mma_kernel,
                         cudaFuncAttributeMaxDynamicSharedMemorySize, SM_BYTES);

    prep_kernel<<<95, 256>>>(ent, rel, h, r);

    dim3 grid(NCT, TSZ / BM);       // 209 x 2 = 418 CTAs, one tile each
    transe_mma_kernel<<<grid, 256, SM_BYTES>>>(out);
}

// round 14
// speedup vs baseline: 1.0156x; 1.0156x over previous
#include <cuda_runtime.h>
#include <cstdint>
#include <math.h>

#define ENT   20000
#define ENTP  20064       // padded to NCT*BN
#define RELN  500
#define DIM   64
#define TSZ   256
#define BM    128
#define BN    96          // 12 n8-tiles; 209 col tiles cover 20064 >= 20000
#define NCT   209
#define PW    36          // smem pitch in 4B words (72 bf16); 36%32=4 -> bank-bijective

// SMEM word offsets
#define OFF_A   0                     // [128][PW] bf16x2 words of hr
#define OFF_B   (BM * PW)             // [96][PW] bf16x2 words of ent tile
#define OFF_NH  (OFF_B + BN * PW)     // [128] f32
#define OFF_NE  (OFF_NH + BM)         // [96] f32
#define SM_WORDS (OFF_NE + BN)
#define SM_BYTES (SM_WORDS * 4)       // 33152

// Precomputed globals (no allocation allowed)
__device__ uint32_t g_entb[ENTP * 32];   // ent_emb as bf16x2 words, zero-padded
__device__ uint32_t g_hrb[TSZ * 32];     // hr = ent[h]+rel[r] as bf16x2 words
__device__ float    g_ne[ENTP];          // ||ent_j||^2 (0 on pad)
__device__ float    g_nh[TSZ];           // ||hr_i||^2

__device__ __forceinline__ float sqrt_approx(float x) {
    float y;
    asm("sqrt.approx.f32 %0, %1;" : "=f"(y) : "f"(x));
    return y;
}
__device__ __forceinline__ uint32_t bf16x2(float lo, float hi) {
    uint32_t u;
    asm("cvt.rn.bf16x2.f32 %0, %1, %2;" : "=r"(u) : "f"(hi), "f"(lo));
    return u;
}
__device__ __forceinline__ void mma_bf16(float* d, const uint32_t* a,
                                         uint32_t b0, uint32_t b1) {
    asm volatile(
        "mma.sync.aligned.m16n8k16.row.col.f32.bf16.bf16.f32 "
        "{%0,%1,%2,%3}, {%4,%5,%6,%7}, {%8,%9}, {%0,%1,%2,%3};"
        : "+f"(d[0]), "+f"(d[1]), "+f"(d[2]), "+f"(d[3])
        : "r"(a[0]), "r"(a[1]), "r"(a[2]), "r"(a[3]), "r"(b0), "r"(b1));
}

// ---------------------------------------------------------------------------
// prep: blocks [0,79)  -> convert ent row j to bf16x2 + ne[j] (zeros on pad)
//       blocks [79,95) -> hr rows (16 thr/row): bf16x2 + nh
// ---------------------------------------------------------------------------
__global__ void __launch_bounds__(256)
prep_kernel(const float* __restrict__ ent, const float* __restrict__ rel,
            const int* __restrict__ h, const int* __restrict__ r) {
    const int b   = blockIdx.x;
    const int tid = threadIdx.x;

    if (b < 79) {
        int j = b * 256 + tid;          // 0..20223
        if (j < ENTP) {
            uint32_t w[32];
            float s = 0.0f;
            if (j < ENT) {
                const float4* e = (const float4*)(ent + (size_t)j * DIM);
#pragma unroll
                for (int k = 0; k < 16; k++) {
                    float4 v = e[k];
                    s += v.x * v.x + v.y * v.y + v.z * v.z + v.w * v.w;
                    w[2 * k]     = bf16x2(v.x, v.y);
                    w[2 * k + 1] = bf16x2(v.z, v.w);
                }
            } else {
#pragma unroll
                for (int k = 0; k < 32; k++) w[k] = 0u;
            }
            uint4* dst = (uint4*)(g_entb + (size_t)j * 32);
#pragma unroll
            for (int k = 0; k < 8; k++)
                dst[k] = make_uint4(w[4 * k], w[4 * k + 1], w[4 * k + 2], w[4 * k + 3]);
            g_ne[j] = s;
        }
    } else {
        int row = (b - 79) * 16 + (tid >> 4);   // 0..255
        int q   = tid & 15;
        int hI  = h[row];
        int rI  = r[row];
        float4 a = *(const float4*)(ent + (size_t)hI * DIM + q * 4);
        float4 c = *(const float4*)(rel + (size_t)rI * DIM + q * 4);
        float4 v = make_float4(a.x + c.x, a.y + c.y, a.z + c.z, a.w + c.w);
        float s = v.x * v.x + v.y * v.y + v.z * v.z + v.w * v.w;
#pragma unroll
        for (int o = 8; o >= 1; o >>= 1) s += __shfl_xor_sync(0xffffffffu, s, o, 16);
        if (q == 0) g_nh[row] = s;
        uint32_t* dst = g_hrb + (size_t)row * 32 + q * 2;
        dst[0] = bf16x2(v.x, v.y);
        dst[1] = bf16x2(v.z, v.w);
    }
}

// ---------------------------------------------------------------------------
// score[i][j] = sqrt(nh[i] + ne[j] - 2 * dot(hr_i, ent_j))
// All operands pre-packed bf16; load phase is pure coalesced LDG.128+STS.128.
// Tile 128 x 96 per CTA; 418 CTAs, 3 resident per SM.
// ---------------------------------------------------------------------------
__global__ void __launch_bounds__(256, 3)
transe_mma_kernel(float* __restrict__ out) {
    extern __shared__ uint32_t smw[];
    uint32_t* sA  = smw + OFF_A;
    uint32_t* sB  = smw + OFF_B;
    float*    sNH = (float*)(smw + OFF_NH);
    float*    sNE = (float*)(smw + OFF_NE);

    const int tid  = threadIdx.x;
    const int lane = tid & 31;
    const int warp = tid >> 5;
    const int jT   = blockIdx.x * BN;
    const int iT   = blockIdx.y * BM;

    // ---- B tile: 96 rows x 32 words = 768 uint4 ----
#pragma unroll
    for (int it = 0; it < 3; it++) {
        int idx = it * 256 + tid;
        int row = idx >> 3;
        int q   = idx & 7;
        uint4 v = *(const uint4*)(g_entb + (size_t)(jT + row) * 32 + q * 4);
        *(uint4*)(sB + row * PW + q * 4) = v;
    }
    // ---- A tile: 128 rows x 32 words = 1024 uint4 ----
#pragma unroll
    for (int it = 0; it < 4; it++) {
        int idx = it * 256 + tid;
        int row = idx >> 3;
        int q   = idx & 7;
        uint4 v = *(const uint4*)(g_hrb + (size_t)(iT + row) * 32 + q * 4);
        *(uint4*)(sA + row * PW + q * 4) = v;
    }
    if (tid < BN)  sNE[tid] = g_ne[jT + tid];
    if (tid < BM)  sNH[tid] = g_nh[iT + tid];
    __syncthreads();

    // ---- mainloop: warp (wm, wn); warp tile 32 x 48; 4 k16 chunks ----
    const int wm  = warp >> 1;      // 0..3
    const int wn  = warp & 1;       // 0..1
    const int grp = lane >> 2;      // 0..7
    const int t4  = lane & 3;       // 0..3

    float d[2][6][4];
#pragma unroll
    for (int f = 0; f < 2; f++)
#pragma unroll
        for (int g = 0; g < 6; g++)
#pragma unroll
            for (int e = 0; e < 4; e++) d[f][g][e] = 0.0f;

#pragma unroll
    for (int ch = 0; ch < 4; ch++) {
        const int k0 = ch * 8 + t4;     // bf16x2-word index within row
        uint32_t a[2][4];
#pragma unroll
        for (int f = 0; f < 2; f++) {
            int base = (wm * 32 + f * 16 + grp) * PW;
            a[f][0] = sA[base + k0];
            a[f][1] = sA[base + 8 * PW + k0];
            a[f][2] = sA[base + k0 + 4];
            a[f][3] = sA[base + 8 * PW + k0 + 4];
        }
#pragma unroll
        for (int g = 0; g < 6; g++) {
            int bbase = (wn * 48 + g * 8 + grp) * PW;
            uint32_t b0 = sB[bbase + k0];
            uint32_t b1 = sB[bbase + k0 + 4];
            mma_bf16(d[0][g], a[0], b0, b1);
            mma_bf16(d[1][g], a[1], b0, b1);
        }
    }

    // ---- epilogue: c0/c1 at (row, 2*t4 / +1); c2/c3 at row+8 ----
#pragma unroll
    for (int f = 0; f < 2; f++) {
        int rl0 = wm * 32 + f * 16 + grp;
        int rl1 = rl0 + 8;
        float nh0 = sNH[rl0];
        float nh1 = sNH[rl1];
        float* o0 = out + (size_t)(iT + rl0) * ENT + jT;
        float* o1 = out + (size_t)(iT + rl1) * ENT + jT;
#pragma unroll
        for (int g = 0; g < 6; g++) {
            int cl = wn * 48 + g * 8 + t4 * 2;
            if (jT + cl < ENT) {
                float2 ne2 = *(const float2*)(sNE + cl);
                float2 s0, s1;
                s0.x = sqrt_approx(fmaxf(nh0 + ne2.x - 2.0f * d[f][g][0], 0.0f));
                s0.y = sqrt_approx(fmaxf(nh0 + ne2.y - 2.0f * d[f][g][1], 0.0f));
                s1.x = sqrt_approx(fmaxf(nh1 + ne2.x - 2.0f * d[f][g][2], 0.0f));
                s1.y = sqrt_approx(fmaxf(nh1 + ne2.y - 2.0f * d[f][g][3], 0.0f));
                *(float2*)(o0 + cl) = s0;
                *(float2*)(o1 + cl) = s1;
            }
        }
    }
}

// ---------------------------------------------------------------------------
// Inputs (metadata order): ent_emb f32[20000*64], rel_emb f32[500*64],
//                          h i32[256], r i32[256], t i32[256], (batch_size)
// Output: f32[256*20000]
// ---------------------------------------------------------------------------
extern "C" void kernel_launch(void* const* d_in, const int* in_sizes, int n_in,
                              void* d_out, int out_size) {
    const float* ent = (const float*)d_in[0];
    const float* rel = (const float*)d_in[1];
    const int*   h   = (const int*)d_in[2];
    const int*   r   = (const int*)d_in[3];
    float*       out = (float*)d_out;

    cudaFuncSetAttribute(transe_mma_kernel,
                         cudaFuncAttributeMaxDynamicSharedMemorySize, SM_BYTES);

    prep_kernel<<<95, 256>>>(ent, rel, h, r);

    dim3 grid(NCT, TSZ / BM);       // 209 x 2 = 418 CTAs, one tile each
    transe_mma_kernel<<<grid, 256, SM_BYTES>>>(out);
}

// round 15
// speedup vs baseline: 1.1581x; 1.1403x over previous
#include <cuda_runtime.h>
#include <cstdint>
#include <math.h>

#define ENT   20000
#define ENTP  20064       // padded to NCT*BN
#define RELN  500
#define DIM   64
#define TSZ   256
#define BM    128
#define BN    96          // 12 n8-tiles; 209 col tiles cover 20064 >= 20000
#define NCT   209
#define PW    36          // smem pitch in 4B words (72 bf16); 36%32=4 -> bank-bijective

// SMEM word offsets
#define OFF_A   0                     // [128][PW] bf16x2 words of hr
#define OFF_B   (BM * PW)             // [96][PW] bf16x2 words of ent tile
#define OFF_NH  (OFF_B + BN * PW)     // [128] f32
#define OFF_NE  (OFF_NH + BM)         // [96] f32
#define SM_WORDS (OFF_NE + BN)
#define SM_BYTES (SM_WORDS * 4)       // 33152

// Precomputed globals (no allocation allowed)
__device__ uint32_t g_entb[ENTP * 32];   // ent_emb as bf16x2 words, zero-padded
__device__ uint32_t g_hrb[TSZ * 32];     // hr = ent[h]+rel[r] as bf16x2 words
__device__ float    g_ne[ENTP];          // ||ent_j||^2 (0 on pad)
__device__ float    g_nh[TSZ];           // ||hr_i||^2

__device__ __forceinline__ float sqrt_approx(float x) {
    float y;
    asm("sqrt.approx.f32 %0, %1;" : "=f"(y) : "f"(x));
    return y;
}
__device__ __forceinline__ uint32_t bf16x2(float lo, float hi) {
    uint32_t u;
    asm("cvt.rn.bf16x2.f32 %0, %1, %2;" : "=r"(u) : "f"(hi), "f"(lo));
    return u;
}
__device__ __forceinline__ void mma_bf16(float* d, const uint32_t* a,
                                         uint32_t b0, uint32_t b1) {
    asm volatile(
        "mma.sync.aligned.m16n8k16.row.col.f32.bf16.bf16.f32 "
        "{%0,%1,%2,%3}, {%4,%5,%6,%7}, {%8,%9}, {%0,%1,%2,%3};"
        : "+f"(d[0]), "+f"(d[1]), "+f"(d[2]), "+f"(d[3])
        : "r"(a[0]), "r"(a[1]), "r"(a[2]), "r"(a[3]), "r"(b0), "r"(b1));
}

// ---------------------------------------------------------------------------
// prep: blocks [0,314) -> ent conversion, 4 threads per row (coalesced):
//         lane-quarter q of row j loads 4 f32x4 (64B contig), writes 2 uint4.
//         ne[j] via 4-lane shfl reduce. Pad rows write zeros.
//       blocks [314,330) -> hr rows (16 thr/row): bf16x2 + nh
// ---------------------------------------------------------------------------
__global__ void __launch_bounds__(256)
prep_kernel(const float* __restrict__ ent, const float* __restrict__ rel,
            const int* __restrict__ h, const int* __restrict__ r) {
    const int b   = blockIdx.x;
    const int tid = threadIdx.x;

    if (b < 314) {
        int idx = b * 256 + tid;        // 80384 slots >= ENTP*4
        int j   = idx >> 2;             // row
        int q   = idx & 3;              // quarter
        if (j < ENTP) {
            uint4 w0, w1;
            float s = 0.0f;
            if (j < ENT) {
                const float4* e = (const float4*)(ent + (size_t)j * DIM + q * 16);
                float4 v0 = e[0], v1 = e[1], v2 = e[2], v3 = e[3];
                s = v0.x*v0.x + v0.y*v0.y + v0.z*v0.z + v0.w*v0.w
                  + v1.x*v1.x + v1.y*v1.y + v1.z*v1.z + v1.w*v1.w
                  + v2.x*v2.x + v2.y*v2.y + v2.z*v2.z + v2.w*v2.w
                  + v3.x*v3.x + v3.y*v3.y + v3.z*v3.z + v3.w*v3.w;
                w0 = make_uint4(bf16x2(v0.x, v0.y), bf16x2(v0.z, v0.w),
                                bf16x2(v1.x, v1.y), bf16x2(v1.z, v1.w));
                w1 = make_uint4(bf16x2(v2.x, v2.y), bf16x2(v2.z, v2.w),
                                bf16x2(v3.x, v3.y), bf16x2(v3.z, v3.w));
            } else {
                w0 = make_uint4(0u, 0u, 0u, 0u);
                w1 = w0;
            }
            uint4* dst = (uint4*)(g_entb + (size_t)j * 32 + q * 8);
            dst[0] = w0;
            dst[1] = w1;
            s += __shfl_xor_sync(0xffffffffu, s, 1, 4);
            s += __shfl_xor_sync(0xffffffffu, s, 2, 4);
            if (q == 0) g_ne[j] = s;
        }
    } else {
        int row = (b - 314) * 16 + (tid >> 4);  // 0..255
        int q   = tid & 15;
        int hI  = h[row];
        int rI  = r[row];
        float4 a = *(const float4*)(ent + (size_t)hI * DIM + q * 4);
        float4 c = *(const float4*)(rel + (size_t)rI * DIM + q * 4);
        float4 v = make_float4(a.x + c.x, a.y + c.y, a.z + c.z, a.w + c.w);
        float s = v.x * v.x + v.y * v.y + v.z * v.z + v.w * v.w;
#pragma unroll
        for (int o = 8; o >= 1; o >>= 1) s += __shfl_xor_sync(0xffffffffu, s, o, 16);
        if (q == 0) g_nh[row] = s;
        uint32_t* dst = g_hrb + (size_t)row * 32 + q * 2;
        dst[0] = bf16x2(v.x, v.y);
        dst[1] = bf16x2(v.z, v.w);
    }
}

// ---------------------------------------------------------------------------
// score[i][j] = sqrt(nh[i] + ne[j] - 2 * dot(hr_i, ent_j))
// All operands pre-packed bf16; load phase is pure coalesced LDG.128+STS.128.
// Tile 128 x 96 per CTA; 418 CTAs, 3 resident per SM.
// ---------------------------------------------------------------------------
__global__ void __launch_bounds__(256, 3)
transe_mma_kernel(float* __restrict__ out) {
    extern __shared__ uint32_t smw[];
    uint32_t* sA  = smw + OFF_A;
    uint32_t* sB  = smw + OFF_B;
    float*    sNH = (float*)(smw + OFF_NH);
    float*    sNE = (float*)(smw + OFF_NE);

    const int tid  = threadIdx.x;
    const int lane = tid & 31;
    const int warp = tid >> 5;
    const int jT   = blockIdx.x * BN;
    const int iT   = blockIdx.y * BM;

    if (tid < BN)  sNE[tid] = g_ne[jT + tid];
    if (tid < BM)  sNH[tid] = g_nh[iT + tid];

    // ---- B tile: 96 rows x 32 words = 768 uint4 ----
#pragma unroll
    for (int it = 0; it < 3; it++) {
        int idx = it * 256 + tid;
        int row = idx >> 3;
        int q   = idx & 7;
        uint4 v = *(const uint4*)(g_entb + (size_t)(jT + row) * 32 + q * 4);
        *(uint4*)(sB + row * PW + q * 4) = v;
    }
    // ---- A tile: 128 rows x 32 words = 1024 uint4 ----
#pragma unroll
    for (int it = 0; it < 4; it++) {
        int idx = it * 256 + tid;
        int row = idx >> 3;
        int q   = idx & 7;
        uint4 v = *(const uint4*)(g_hrb + (size_t)(iT + row) * 32 + q * 4);
        *(uint4*)(sA + row * PW + q * 4) = v;
    }
    __syncthreads();

    // ---- mainloop: warp (wm, wn); warp tile 32 x 48; 4 k16 chunks ----
    const int wm  = warp >> 1;      // 0..3
    const int wn  = warp & 1;       // 0..1
    const int grp = lane >> 2;      // 0..7
    const int t4  = lane & 3;       // 0..3

    float d[2][6][4];
#pragma unroll
    for (int f = 0; f < 2; f++)
#pragma unroll
        for (int g = 0; g < 6; g++)
#pragma unroll
            for (int e = 0; e < 4; e++) d[f][g][e] = 0.0f;

#pragma unroll
    for (int ch = 0; ch < 4; ch++) {
        const int k0 = ch * 8 + t4;     // bf16x2-word index within row
        uint32_t a[2][4];
#pragma unroll
        for (int f = 0; f < 2; f++) {
            int base = (wm * 32 + f * 16 + grp) * PW;
            a[f][0] = sA[base + k0];
            a[f][1] = sA[base + 8 * PW + k0];
            a[f][2] = sA[base + k0 + 4];
            a[f][3] = sA[base + 8 * PW + k0 + 4];
        }
#pragma unroll
        for (int g = 0; g < 6; g++) {
            int bbase = (wn * 48 + g * 8 + grp) * PW;
            uint32_t b0 = sB[bbase + k0];
            uint32_t b1 = sB[bbase + k0 + 4];
            mma_bf16(d[0][g], a[0], b0, b1);
            mma_bf16(d[1][g], a[1], b0, b1);
        }
    }

    // ---- epilogue: c0/c1 at (row, 2*t4 / +1); c2/c3 at row+8 ----
#pragma unroll
    for (int f = 0; f < 2; f++) {
        int rl0 = wm * 32 + f * 16 + grp;
        int rl1 = rl0 + 8;
        float nh0 = sNH[rl0];
        float nh1 = sNH[rl1];
        float* o0 = out + (size_t)(iT + rl0) * ENT + jT;
        float* o1 = out + (size_t)(iT + rl1) * ENT + jT;
#pragma unroll
        for (int g = 0; g < 6; g++) {
            int cl = wn * 48 + g * 8 + t4 * 2;
            if (jT + cl < ENT) {
                float2 ne2 = *(const float2*)(sNE + cl);
                float2 s0, s1;
                s0.x = sqrt_approx(fmaxf(nh0 + ne2.x - 2.0f * d[f][g][0], 0.0f));
                s0.y = sqrt_approx(fmaxf(nh0 + ne2.y - 2.0f * d[f][g][1], 0.0f));
                s1.x = sqrt_approx(fmaxf(nh1 + ne2.x - 2.0f * d[f][g][2], 0.0f));
                s1.y = sqrt_approx(fmaxf(nh1 + ne2.y - 2.0f * d[f][g][3], 0.0f));
                *(float2*)(o0 + cl) = s0;
                *(float2*)(o1 + cl) = s1;
            }
        }
    }
}

// ---------------------------------------------------------------------------
// Inputs (metadata order): ent_emb f32[20000*64], rel_emb f32[500*64],
//                          h i32[256], r i32[256], t i32[256], (batch_size)
// Output: f32[256*20000]
// ---------------------------------------------------------------------------
extern "C" void kernel_launch(void* const* d_in, const int* in_sizes, int n_in,
                              void* d_out, int out_size) {
    const float* ent = (const float*)d_in[0];
    const float* rel = (const float*)d_in[1];
    const int*   h   = (const int*)d_in[2];
    const int*   r   = (const int*)d_in[3];
    float*       out = (float*)d_out;

    cudaFuncSetAttribute(transe_mma_kernel,
                         cudaFuncAttributeMaxDynamicSharedMemorySize, SM_BYTES);

    prep_kernel<<<330, 256>>>(ent, rel, h, r);

    dim3 grid(NCT, TSZ / BM);       // 209 x 2 = 418 CTAs, one tile each
    transe_mma_kernel<<<grid, 256, SM_BYTES>>>(out);
}

// round 17
// speedup vs baseline: 1.2871x; 1.1114x over previous
#include <cuda_runtime.h>
#include <cstdint>
#include <math.h>

#define ENT   20000
#define RELN  500
#define DIM   64
#define TSZ   256
#define BM    128
#define BN    96          // 12 n8-tiles; 209 col tiles cover 20064 >= 20000
#define NCT   209
#define PW    36          // smem pitch in 4B words (72 bf16); 36%32=4 -> bank-bijective

// SMEM word offsets
#define OFF_A   0                     // [128][PW] bf16x2 words of hr
#define OFF_B   (BM * PW)             // [96][PW] bf16x2 words of ent tile
#define OFF_NH  (OFF_B + BN * PW)     // [128] f32
#define OFF_NE  (OFF_NH + BM)         // [96] f32
#define SM_WORDS (OFF_NE + BN)
#define SM_BYTES (SM_WORDS * 4)       // 33152

// Precomputed globals (no allocation allowed)
__device__ uint32_t g_hrb[TSZ * 32];     // hr = ent[h]+rel[r] as bf16x2 words
__device__ float    g_nh[TSZ];           // ||hr_i||^2

__device__ __forceinline__ float sqrt_approx(float x) {
    float y;
    asm("sqrt.approx.f32 %0, %1;" : "=f"(y) : "f"(x));
    return y;
}
__device__ __forceinline__ uint32_t bf16x2(float lo, float hi) {
    uint32_t u;
    asm("cvt.rn.bf16x2.f32 %0, %1, %2;" : "=r"(u) : "f"(hi), "f"(lo));
    return u;
}
__device__ __forceinline__ void mma_bf16(float* d, const uint32_t* a,
                                         uint32_t b0, uint32_t b1) {
    asm volatile(
        "mma.sync.aligned.m16n8k16.row.col.f32.bf16.bf16.f32 "
        "{%0,%1,%2,%3}, {%4,%5,%6,%7}, {%8,%9}, {%0,%1,%2,%3};"
        : "+f"(d[0]), "+f"(d[1]), "+f"(d[2]), "+f"(d[3])
        : "r"(a[0]), "r"(a[1]), "r"(a[2]), "r"(a[3]), "r"(b0), "r"(b1));
}

// ---------------------------------------------------------------------------
// prep_hr: 16 blocks, 16 threads/row -> g_hrb (bf16x2) + g_nh. Tiny kernel:
// only the 256 hr rows (the redundant-gather hot spot); ent stays f32.
// ---------------------------------------------------------------------------
__global__ void __launch_bounds__(256)
prep_hr_kernel(const float* __restrict__ ent, const float* __restrict__ rel,
               const int* __restrict__ h, const int* __restrict__ r) {
    int row = blockIdx.x * 16 + (threadIdx.x >> 4);  // 0..255
    int q   = threadIdx.x & 15;
    int hI  = h[row];
    int rI  = r[row];
    float4 a = *(const float4*)(ent + (size_t)hI * DIM + q * 4);
    float4 c = *(const float4*)(rel + (size_t)rI * DIM + q * 4);
    float4 v = make_float4(a.x + c.x, a.y + c.y, a.z + c.z, a.w + c.w);
    float s = v.x * v.x + v.y * v.y + v.z * v.z + v.w * v.w;
#pragma unroll
    for (int o = 8; o >= 1; o >>= 1) s += __shfl_xor_sync(0xffffffffu, s, o, 16);
    if (q == 0) g_nh[row] = s;
    uint32_t* dst = g_hrb + (size_t)row * 32 + q * 2;
    dst[0] = bf16x2(v.x, v.y);
    dst[1] = bf16x2(v.z, v.w);
}

// ---------------------------------------------------------------------------
// score[i][j] = sqrt(nh[i] + ne[j] - 2 * dot(hr_i, ent_j))
// A pre-packed bf16 (coalesced uint4); B converted inline from f32 with fused
// ne shuffle-reduce. Tile 128 x 96 per CTA; 418 CTAs, 3 resident per SM.
// ---------------------------------------------------------------------------
__global__ void __launch_bounds__(256, 3)
transe_mma_kernel(const float* __restrict__ ent, float* __restrict__ out) {
    extern __shared__ uint32_t smw[];
    uint32_t* sA  = smw + OFF_A;
    uint32_t* sB  = smw + OFF_B;
    float*    sNH = (float*)(smw + OFF_NH);
    float*    sNE = (float*)(smw + OFF_NE);

    const int tid  = threadIdx.x;
    const int lane = tid & 31;
    const int warp = tid >> 5;
    const int jT   = blockIdx.x * BN;
    const int iT   = blockIdx.y * BM;

    if (tid < BM) sNH[tid] = g_nh[iT + tid];

    // ---- B tile: 96 rows, f32 LDG + bf16 convert + fused ne reduce ----
#pragma unroll
    for (int it = 0; it < 6; it++) {
        int idx = it * 256 + tid;       // 1536 float4 slots
        int row = idx >> 4;
        int q   = idx & 15;
        int jG  = jT + row;
        float4 v = make_float4(0.f, 0.f, 0.f, 0.f);
        if (jG < ENT) v = *(const float4*)(ent + (size_t)jG * DIM + q * 4);
        float s = v.x * v.x + v.y * v.y + v.z * v.z + v.w * v.w;
#pragma unroll
        for (int o = 8; o >= 1; o >>= 1) s += __shfl_xor_sync(0xffffffffu, s, o, 16);
        if (q == 0) sNE[row] = s;
        uint32_t* dst = sB + row * PW + q * 2;
        dst[0] = bf16x2(v.x, v.y);
        dst[1] = bf16x2(v.z, v.w);
    }
    // ---- A tile: 128 rows x 32 words pre-packed = 1024 uint4 ----
#pragma unroll
    for (int it = 0; it < 4; it++) {
        int idx = it * 256 + tid;
        int row = idx >> 3;
        int q   = idx & 7;
        uint4 v = *(const uint4*)(g_hrb + (size_t)(iT + row) * 32 + q * 4);
        *(uint4*)(sA + row * PW + q * 4) = v;
    }
    __syncthreads();

    // ---- mainloop: warp (wm, wn); warp tile 32 x 48; 4 k16 chunks ----
    const int wm  = warp >> 1;      // 0..3
    const int wn  = warp & 1;       // 0..1
    const int grp = lane >> 2;      // 0..7
    const int t4  = lane & 3;       // 0..3

    float d[2][6][4];
#pragma unroll
    for (int f = 0; f < 2; f++)
#pragma unroll
        for (int g = 0; g < 6; g++)
#pragma unroll
            for (int e = 0; e < 4; e++) d[f][g][e] = 0.0f;

#pragma unroll
    for (int ch = 0; ch < 4; ch++) {
        const int k0 = ch * 8 + t4;     // bf16x2-word index within row
        uint32_t a[2][4];
#pragma unroll
        for (int f = 0; f < 2; f++) {
            int base = (wm * 32 + f * 16 + grp) * PW;
            a[f][0] = sA[base + k0];
            a[f][1] = sA[base + 8 * PW + k0];
            a[f][2] = sA[base + k0 + 4];
            a[f][3] = sA[base + 8 * PW + k0 + 4];
        }
#pragma unroll
        for (int g = 0; g < 6; g++) {
            int bbase = (wn * 48 + g * 8 + grp) * PW;
            uint32_t b0 = sB[bbase + k0];
            uint32_t b1 = sB[bbase + k0 + 4];
            mma_bf16(d[0][g], a[0], b0, b1);
            mma_bf16(d[1][g], a[1], b0, b1);
        }
    }

    // ---- epilogue: c0/c1 at (row, 2*t4 / +1); c2/c3 at row+8 ----
#pragma unroll
    for (int f = 0; f < 2; f++) {
        int rl0 = wm * 32 + f * 16 + grp;
        int rl1 = rl0 + 8;
        float nh0 = sNH[rl0];
        float nh1 = sNH[rl1];
        float* o0 = out + (size_t)(iT + rl0) * ENT + jT;
        float* o1 = out + (size_t)(iT + rl1) * ENT + jT;
#pragma unroll
        for (int g = 0; g < 6; g++) {
            int cl = wn * 48 + g * 8 + t4 * 2;
            if (jT + cl < ENT) {
                float2 ne2 = *(const float2*)(sNE + cl);
                float2 s0, s1;
                s0.x = sqrt_approx(fmaxf(nh0 + ne2.x - 2.0f * d[f][g][0], 0.0f));
                s0.y = sqrt_approx(fmaxf(nh0 + ne2.y - 2.0f * d[f][g][1], 0.0f));
                s1.x = sqrt_approx(fmaxf(nh1 + ne2.x - 2.0f * d[f][g][2], 0.0f));
                s1.y = sqrt_approx(fmaxf(nh1 + ne2.y - 2.0f * d[f][g][3], 0.0f));
                *(float2*)(o0 + cl) = s0;
                *(float2*)(o1 + cl) = s1;
            }
        }
    }
}

// ---------------------------------------------------------------------------
// Inputs (metadata order): ent_emb f32[20000*64], rel_emb f32[500*64],
//                          h i32[256], r i32[256], t i32[256], (batch_size)
// Output: f32[256*20000]
// ---------------------------------------------------------------------------
extern "C" void kernel_launch(void* const* d_in, const int* in_sizes, int n_in,
                              void* d_out, int out_size) {
    const float* ent = (const float*)d_in[0];
    const float* rel = (const float*)d_in[1];
    const int*   h   = (const int*)d_in[2];
    const int*   r   = (const int*)d_in[3];
    float*       out = (float*)d_out;

    cudaFuncSetAttribute(transe_mma_kernel,
                         cudaFuncAttributeMaxDynamicSharedMemorySize, SM_BYTES);

    prep_hr_kernel<<<16, 256>>>(ent, rel, h, r);

    dim3 grid(NCT, TSZ / BM);       // 209 x 2 = 418 CTAs, one tile each
    transe_mma_kernel<<<grid, 256, SM_BYTES>>>(ent, out);
}